// round 5
// baseline (speedup 1.0000x reference)
#include <cuda_runtime.h>
#include <math.h>

// z (16,128,64,64) fp32, codebook (1024,128) fp32
#define C      128
#define KC     1024
#define BATCH  16
#define HW     4096            // 64*64
#define NTOT   (BATCH * HW)    // 65536
#define TN     64              // n rows per block
#define TK     16              // codes per k-tile
#define ES     17              // e_s row stride (pad to dodge bank conflicts)
#define NKT    (KC / TK)       // 64 k-tiles
#define NBLK   (NTOT / TN)     // 1024 blocks
#define M_ZQ   (NTOT * C)      // 8388608 elements of z_q

// Scratch (no allocations allowed -> __device__ globals)
__device__ float d_enorm[KC];          // ||e_k||^2 (serial fp32 sum, ref-style)
__device__ int   d_used[KC];           // usage flags
__device__ float d_partials[NBLK];     // per-block MSE partial sums

// ---------------------------------------------------------------------------
// Prep: per-code squared norm (serial ascending c, mul+add, no fma -> matches
// jnp.sum(codebook**2, axis=1) elementwise-square-then-sum) + zero usage.
__global__ void vq_prep(const float* __restrict__ cb) {
    int k = blockIdx.x * 256 + threadIdx.x;          // 0 .. 1023
    const float* row = cb + k * C;
    float s = 0.f;
    for (int c = 0; c < C; c++) {
        float v = row[c];
        s = __fadd_rn(s, __fmul_rn(v, v));
    }
    d_enorm[k] = s;
    d_used[k] = 0;
}

// ---------------------------------------------------------------------------
// Consolidated main kernel: distances + argmin + gather + output + loss partial.
// 128 threads = 8 (tx: 2 codes each) x 16 (ty: 4 rows each). Grid = 1024.
// smem: z_s 32KB + e_s 8.5KB + misc < 42KB static.
__global__ void __launch_bounds__(128)
vq_main(const float* __restrict__ z, const float* __restrict__ cb,
        float* __restrict__ out) {
    __shared__ float z_s[C * TN];      // [c][i], stride 64
    __shared__ float e_s[C * ES];      // [c][q], stride 17
    __shared__ float zn_s[TN];         // ||z_n||^2 per row
    __shared__ int   idx_s[TN];        // winning code per row
    __shared__ float red[128];         // loss reduction

    const int tid = threadIdx.x;
    const int tx  = tid & 7;           // code group (0..7), 2 codes each
    const int ty  = tid >> 3;          // row group (0..15), 4 rows each
    const int n0  = blockIdx.x * TN;
    const int b   = n0 >> 12;          // TN divides HW -> tile within one b
    const int hw0 = n0 & (HW - 1);
    const float* zb = z + (size_t)b * C * HW + hw0;

    // 1) Load z tile: z_s[c][i] = z[b, c, hw0+i]; coalesced float4
    for (int v = tid; v < C * TN / 4; v += 128) {
        int c  = v >> 4;               // 16 float4 per row
        int i4 = v & 15;
        float4 t = *reinterpret_cast<const float4*>(zb + (size_t)c * HW + i4 * 4);
        *reinterpret_cast<float4*>(&z_s[c * TN + i4 * 4]) = t;
    }
    __syncthreads();

    // 2) ||z_n||^2: serial ascending c, square-then-add (ref-style rounding)
    if (tid < TN) {
        float s = 0.f;
        for (int c = 0; c < C; c++) {
            float v = z_s[c * TN + tid];
            s = __fadd_rn(s, __fmul_rn(v, v));
        }
        zn_s[tid] = s;
    }
    __syncthreads();

    float znL[4];
#pragma unroll
    for (int i = 0; i < 4; i++) znL[i] = zn_s[ty * 4 + i];

    float best[4];
    int   bestk[4];
#pragma unroll
    for (int i = 0; i < 4; i++) { best[i] = INFINITY; bestk[i] = 0; }

    // 3) K loop: load 16-code tile directly from cb (transpose in-kernel)
    for (int kt = 0; kt < NKT; kt++) {
        __syncthreads();
        // 16 rows x 128 c = 512 float4 reads; coalesced; scatter to [c][q]
        for (int p = tid; p < TK * C / 4; p += 128) {
            int r  = p >> 5;           // code row in tile (0..15)
            int cc = p & 31;           // float4 col (0..31)
            float4 t = *reinterpret_cast<const float4*>(
                &cb[(size_t)(kt * TK + r) * C + cc * 4]);
            e_s[(cc * 4 + 0) * ES + r] = t.x;
            e_s[(cc * 4 + 1) * ES + r] = t.y;
            e_s[(cc * 4 + 2) * ES + r] = t.z;
            e_s[(cc * 4 + 3) * ES + r] = t.w;
        }
        __syncthreads();

        // dot(z_n, e_k), serial ascending c with fmaf (cublas-style accumulation)
        float acc[2][4];
#pragma unroll
        for (int j = 0; j < 2; j++)
#pragma unroll
            for (int i = 0; i < 4; i++) acc[j][i] = 0.f;

#pragma unroll 8
        for (int c = 0; c < C; c++) {
            float  e0 = e_s[c * ES + tx * 2];
            float  e1 = e_s[c * ES + tx * 2 + 1];
            float4 zv = *reinterpret_cast<float4*>(&z_s[c * TN + ty * 4]);
            float z4[4] = {zv.x, zv.y, zv.z, zv.w};
#pragma unroll
            for (int i = 0; i < 4; i++) {
                acc[0][i] = fmaf(e0, z4[i], acc[0][i]);
                acc[1][i] = fmaf(e1, z4[i], acc[1][i]);
            }
        }

        // Replicate ref: dists = fl(fl(znorm + enorm) - fl(2*dot))
#pragma unroll
        for (int j = 0; j < 2; j++) {
            const int k = kt * TK + tx * 2 + j;
            float en = __ldg(&d_enorm[k]);
#pragma unroll
            for (int i = 0; i < 4; i++) {
                float t1 = __fadd_rn(znL[i], en);
                float s  = __fadd_rn(t1, __fmul_rn(-2.f, acc[j][i]));
                if (s < best[i]) { best[i] = s; bestk[i] = k; }
                // ascending k + strict '<' => first minimum wins (jnp.argmin)
            }
        }
    }

    // 4) Reduce over the 8 tx lanes; equal scores -> smaller k (first wins)
#pragma unroll
    for (int i = 0; i < 4; i++) {
        float s = best[i];
        int   k = bestk[i];
#pragma unroll
        for (int m = 4; m >= 1; m >>= 1) {
            float so = __shfl_xor_sync(0xffffffff, s, m);
            int   ko = __shfl_xor_sync(0xffffffff, k, m);
            if (so < s || (so == s && ko < k)) { s = so; k = ko; }
        }
        if (tx == 0) {
            idx_s[ty * 4 + i] = k;
            d_used[k] = 1;             // benign race: all writers store 1
        }
    }
    __syncthreads();

    // 5) Gather + straight-through write + loss partial.
    //    out element (b, c, hw0+row); per warp: fixed c, 32 consecutive rows.
    float* ob = out + (size_t)b * C * HW + hw0;
    float lsum = 0.f;
    for (int p = tid; p < TN * C; p += 128) {
        int row = p & (TN - 1);
        int c   = p >> 6;
        float zq = __ldg(&cb[(size_t)idx_s[row] * C + c]);
        float zv = z_s[c * TN + row];
        float d  = __fadd_rn(zq, -zv);           // fl(z_q - z)
        ob[(size_t)c * HW + row] = __fadd_rn(zv, d);  // fl(z + fl(z_q - z))
        lsum += d * d;
    }

    red[tid] = lsum;
    __syncthreads();
#pragma unroll
    for (int s = 64; s > 0; s >>= 1) {
        if (tid < s) red[tid] += red[tid + s];
        __syncthreads();
    }
    if (tid == 0) d_partials[blockIdx.x] = red[0];
}

// ---------------------------------------------------------------------------
// Final scalars: vq_loss = 1.25 * mean((zq - z)^2), usage = (#used)/K
__global__ void vq_final(float* __restrict__ out, int out_size) {
    __shared__ float fred[256];
    __shared__ int   ired[256];
    const int t = threadIdx.x;

    float fs = 0.f;
#pragma unroll
    for (int p = t; p < NBLK; p += 256) fs += d_partials[p];
    int cnt = 0;
#pragma unroll
    for (int k = t; k < KC; k += 256) cnt += d_used[k];
    fred[t] = fs;
    ired[t] = cnt;
    __syncthreads();
#pragma unroll
    for (int s = 128; s > 0; s >>= 1) {
        if (t < s) { fred[t] += fred[t + s]; ired[t] += ired[t + s]; }
        __syncthreads();
    }
    if (t == 0 && out_size >= M_ZQ + 2) {
        float mse = fred[0] / (float)((size_t)NTOT * C);
        out[M_ZQ]     = 1.25f * mse;             // codebook + 0.25*commitment
        out[M_ZQ + 1] = (float)ired[0] / (float)KC;
    }
}

// ---------------------------------------------------------------------------
extern "C" void kernel_launch(void* const* d_in, const int* in_sizes, int n_in,
                              void* d_out, int out_size) {
    // Bind inputs by element count (robust to ordering)
    const float* z;
    const float* cb;
    if (in_sizes[0] == KC * C) {
        cb = (const float*)d_in[0];
        z  = (const float*)d_in[1];
    } else {
        z  = (const float*)d_in[0];
        cb = (const float*)d_in[1];
    }
    float* out = (float*)d_out;

    vq_prep<<<KC / 256, 256>>>(cb);
    vq_main<<<NBLK, 128>>>(z, cb, out);
    vq_final<<<1, 256>>>(out, out_size);
}